// round 1
// baseline (speedup 1.0000x reference)
#include <cuda_runtime.h>

#define S_ 160
#define H_ 768

// scratch (device globals — no allocation allowed)
__device__ float g_yrot[S_ * H_];
__device__ float g_L[S_ * H_];
__device__ float g_R[S_ * H_];

typedef unsigned long long u64;

__device__ __forceinline__ void fma2(u64& d, u64 a, u64 b) {
    asm volatile("fma.rn.f32x2 %0, %1, %2, %0;" : "+l"(d) : "l"(a), "l"(b));
}
__device__ __forceinline__ u64 pack2(float x, float y) {
    u64 r; asm("mov.b64 %0, {%1, %2};" : "=l"(r) : "f"(x), "f"(y)); return r;
}
__device__ __forceinline__ float2 unpack2(u64 v) {
    float2 f; asm("mov.b64 {%0, %1}, %2;" : "=f"(f.x), "=f"(f.y) : "l"(v)); return f;
}
__device__ __forceinline__ float sigf(float x) { return 1.0f / (1.0f + __expf(-x)); }

__device__ __forceinline__ float4 reluadd4(float4 a, float4 b) {
    float4 r;
    r.x = fmaxf(a.x + b.x, 0.f);
    r.y = fmaxf(a.y + b.y, 0.f);
    r.z = fmaxf(a.z + b.z, 0.f);
    r.w = fmaxf(a.w + b.w, 0.f);
    return r;
}

// ---------------------------------------------------------------------------
// Kernel A: RoPE.  grid 160, block 384 (one thread per (2k,2k+1) pair)
// ---------------------------------------------------------------------------
__global__ void rope_kernel(const float* __restrict__ y) {
    int s = blockIdx.x;
    int k = threadIdx.x;  // 0..383
    // inv_freq = 10000^(-2k/768)
    float inv = expf(-(2.0f * (float)k / 768.0f) * 9.210340371976184f);
    float th = (float)s * inv;
    float sn, cs;
    sincosf(th, &sn, &cs);
    float y0 = y[s * H_ + 2 * k];
    float y1 = y[s * H_ + 2 * k + 1];
    g_yrot[s * H_ + 2 * k]     = y0 * cs - y1 * sn;
    g_yrot[s * H_ + 2 * k + 1] = y1 * cs + y0 * sn;
}

// ---------------------------------------------------------------------------
// Kernel B: L = yrot @ W1[:, :768]^T ; R = yrot @ W1[:, 768:]^T + b1
// GEMM 160 x 1536 x 768.  BM=32, BN=128, BK=16.  grid (5, 12), 256 threads.
// Ntile 0..5 -> L part, 6..11 -> R part.
// ---------------------------------------------------------------------------
__global__ __launch_bounds__(256) void lr_kernel(const float* __restrict__ W1,
                                                 const float* __restrict__ b1) {
    __shared__ float As[16][34];    // [k][s-row], padded
    __shared__ float Bs[16][136];   // [k][n], padded

    int t = threadIdx.x;
    int Mtile = blockIdx.x;          // 0..4
    int nbase = blockIdx.y * 128;    // 0..1408
    int isR = (nbase >= 768);
    int obase = isR ? (nbase - 768) : nbase;
    int cofs = isR ? 768 : 0;
    int tx = t & 15, ty = t >> 4;

    float acc[2][8];
#pragma unroll
    for (int r = 0; r < 2; r++)
#pragma unroll
        for (int c = 0; c < 8; c++) acc[r][c] = 0.f;

    for (int k0 = 0; k0 < H_; k0 += 16) {
#pragma unroll
        for (int it = 0; it < 2; it++) {
            int q = t + it * 256;
            int row = q >> 4, kk = q & 15;
            As[kk][row] = g_yrot[(Mtile * 32 + row) * H_ + k0 + kk];
        }
#pragma unroll
        for (int it = 0; it < 8; it++) {
            int q = t + it * 256;
            int nn = q >> 4, kk = q & 15;
            Bs[kk][nn] = W1[(obase + nn) * 1536 + cofs + k0 + kk];
        }
        __syncthreads();
#pragma unroll
        for (int kk = 0; kk < 16; kk++) {
            float a0 = As[kk][ty * 2 + 0];
            float a1 = As[kk][ty * 2 + 1];
            float b[8];
            *(float4*)&b[0] = *(const float4*)&Bs[kk][tx * 8];
            *(float4*)&b[4] = *(const float4*)&Bs[kk][tx * 8 + 4];
#pragma unroll
            for (int c = 0; c < 8; c++) {
                acc[0][c] += a0 * b[c];
                acc[1][c] += a1 * b[c];
            }
        }
        __syncthreads();
    }

    int s0 = Mtile * 32 + ty * 2;
#pragma unroll
    for (int c = 0; c < 8; c++) {
        int o = obase + tx * 8 + c;
        if (isR) {
            float bb = b1[o];
            g_R[(s0 + 0) * H_ + o] = acc[0][c] + bb;
            g_R[(s0 + 1) * H_ + o] = acc[1][c] + bb;
        } else {
            g_L[(s0 + 0) * H_ + o] = acc[0][c];
            g_L[(s0 + 1) * H_ + o] = acc[1][c];
        }
    }
}

// ---------------------------------------------------------------------------
// Kernel C: fused main GEMM.
//   out[p, o] = sigmoid( sum_h relu(L[i,h]+R[j,h]) * W2[o,h] + b2[o] ),
//   p = i*160+j, M = 25600, N = 256 (first 2 full 128-tiles of 260), K = 768.
// BM=128, BN=128, BK=16, 256 threads, 8x8 microtile, f32x2 packed FMA.
// grid (200, 2).
// ---------------------------------------------------------------------------
__global__ __launch_bounds__(256, 2) void main_kernel(const float* __restrict__ W2,
                                                      const float* __restrict__ b2,
                                                      float* __restrict__ out) {
    __shared__ __align__(16) float As[16][132];  // [k][pair-row]
    __shared__ __align__(16) float Bs[16][132];  // [k][o-col]

    int t = threadIdx.x;
    int Mtile = blockIdx.x;   // 0..199
    int Ntile = blockIdx.y;   // 0..1
    int tx = t & 15, ty = t >> 4;

    // tile-build mapping: element (rowA + {0,64}, seg*4 .. seg*4+3)
    int rowA = t >> 2;        // 0..63
    int seg = t & 3;
    int segOff = seg * 4;

    int p0 = Mtile * 128 + rowA;
    int p1 = p0 + 64;
    int i0 = p0 / 160, j0 = p0 - i0 * 160;
    int i1 = p1 / 160, j1 = p1 - i1 * 160;
    const float* Lp0 = g_L + i0 * H_;
    const float* Rp0 = g_R + j0 * H_;
    const float* Lp1 = g_L + i1 * H_;
    const float* Rp1 = g_R + j1 * H_;
    const float* Wp0 = W2 + (Ntile * 128 + rowA) * H_;
    const float* Wp1 = Wp0 + 64 * H_;

    u64 acc[4][8];
#pragma unroll
    for (int r = 0; r < 4; r++)
#pragma unroll
        for (int c = 0; c < 8; c++) acc[r][c] = 0ULL;

    // prefetch chunk 0
    float4 aP0 = reluadd4(*(const float4*)(Lp0 + segOff), *(const float4*)(Rp0 + segOff));
    float4 aP1 = reluadd4(*(const float4*)(Lp1 + segOff), *(const float4*)(Rp1 + segOff));
    float4 bP0 = *(const float4*)(Wp0 + segOff);
    float4 bP1 = *(const float4*)(Wp1 + segOff);

    for (int k0 = 0; k0 < H_; k0 += 16) {
        // stage current chunk to smem
        As[segOff + 0][rowA] = aP0.x; As[segOff + 1][rowA] = aP0.y;
        As[segOff + 2][rowA] = aP0.z; As[segOff + 3][rowA] = aP0.w;
        As[segOff + 0][rowA + 64] = aP1.x; As[segOff + 1][rowA + 64] = aP1.y;
        As[segOff + 2][rowA + 64] = aP1.z; As[segOff + 3][rowA + 64] = aP1.w;
        Bs[segOff + 0][rowA] = bP0.x; Bs[segOff + 1][rowA] = bP0.y;
        Bs[segOff + 2][rowA] = bP0.z; Bs[segOff + 3][rowA] = bP0.w;
        Bs[segOff + 0][rowA + 64] = bP1.x; Bs[segOff + 1][rowA + 64] = bP1.y;
        Bs[segOff + 2][rowA + 64] = bP1.z; Bs[segOff + 3][rowA + 64] = bP1.w;
        __syncthreads();

        // prefetch next chunk while computing
        int kn = k0 + 16;
        if (kn < H_) {
            aP0 = reluadd4(*(const float4*)(Lp0 + kn + segOff), *(const float4*)(Rp0 + kn + segOff));
            aP1 = reluadd4(*(const float4*)(Lp1 + kn + segOff), *(const float4*)(Rp1 + kn + segOff));
            bP0 = *(const float4*)(Wp0 + kn + segOff);
            bP1 = *(const float4*)(Wp1 + kn + segOff);
        }

#pragma unroll
        for (int kk = 0; kk < 16; kk++) {
            ulonglong2 av0 = *(const ulonglong2*)&As[kk][ty * 8];
            ulonglong2 av1 = *(const ulonglong2*)&As[kk][ty * 8 + 4];
            float4 bf0 = *(const float4*)&Bs[kk][tx * 8];
            float4 bf1 = *(const float4*)&Bs[kk][tx * 8 + 4];
            u64 a2[4] = {av0.x, av0.y, av1.x, av1.y};
            u64 bD[8];
            bD[0] = pack2(bf0.x, bf0.x); bD[1] = pack2(bf0.y, bf0.y);
            bD[2] = pack2(bf0.z, bf0.z); bD[3] = pack2(bf0.w, bf0.w);
            bD[4] = pack2(bf1.x, bf1.x); bD[5] = pack2(bf1.y, bf1.y);
            bD[6] = pack2(bf1.z, bf1.z); bD[7] = pack2(bf1.w, bf1.w);
#pragma unroll
            for (int rp = 0; rp < 4; rp++)
#pragma unroll
                for (int c = 0; c < 8; c++)
                    fma2(acc[rp][c], a2[rp], bD[c]);
        }
        __syncthreads();
    }

    // epilogue: +b2, sigmoid, scatter into (65,160,160,4) layout
    int ob = Ntile * 128 + tx * 8;   // multiple of 8 -> o%4 == c%4
    float bias[8];
#pragma unroll
    for (int c = 0; c < 8; c++) bias[c] = b2[ob + c];
    int rI0 = ob >> 2;               // rel index for cols 0..3; +1 for 4..7

#pragma unroll
    for (int rp = 0; rp < 4; rp++) {
        float2 v[8];
#pragma unroll
        for (int c = 0; c < 8; c++) v[c] = unpack2(acc[rp][c]);
#pragma unroll
        for (int h = 0; h < 2; h++) {
            int r = ty * 8 + rp * 2 + h;
            int p = Mtile * 128 + r;
            int i = p / 160, j = p - i * 160;
            float4 o0, o1;
            o0.x = sigf((h ? v[0].y : v[0].x) + bias[0]);
            o0.y = sigf((h ? v[1].y : v[1].x) + bias[1]);
            o0.z = sigf((h ? v[2].y : v[2].x) + bias[2]);
            o0.w = sigf((h ? v[3].y : v[3].x) + bias[3]);
            o1.x = sigf((h ? v[4].y : v[4].x) + bias[4]);
            o1.y = sigf((h ? v[5].y : v[5].x) + bias[5]);
            o1.z = sigf((h ? v[6].y : v[6].x) + bias[6]);
            o1.w = sigf((h ? v[7].y : v[7].x) + bias[7]);
            *(float4*)&out[(((rI0 + 0) * 160 + i) * 160 + j) * 4] = o0;
            *(float4*)&out[(((rI0 + 1) * 160 + i) * 160 + j) * 4] = o1;
        }
    }
}

// ---------------------------------------------------------------------------
// Kernel D: tail outputs o = 256..259 (rel index 64).  grid 160 (i), 256 thr.
// Warp-per-j, lane-split over h with shfl reduction.
// ---------------------------------------------------------------------------
__global__ __launch_bounds__(256) void tail_kernel(const float* __restrict__ W2,
                                                   const float* __restrict__ b2,
                                                   float* __restrict__ out) {
    __shared__ float Lsh[H_];
    __shared__ float W2sh[4][H_];
    int i = blockIdx.x;
    int t = threadIdx.x;

    for (int h = t; h < H_; h += 256) Lsh[h] = g_L[i * H_ + h];
    for (int q = t; q < 4 * H_; q += 256) {
        int row = q / H_, h = q - row * H_;
        W2sh[row][h] = W2[(256 + row) * H_ + h];
    }
    __syncthreads();

    int w = t >> 5, lane = t & 31;
    for (int j = w; j < 160; j += 8) {
        const float* Rr = g_R + j * H_;
        float a0 = 0.f, a1 = 0.f, a2 = 0.f, a3 = 0.f;
        for (int h = lane; h < H_; h += 32) {
            float a = fmaxf(Lsh[h] + Rr[h], 0.f);
            a0 += a * W2sh[0][h];
            a1 += a * W2sh[1][h];
            a2 += a * W2sh[2][h];
            a3 += a * W2sh[3][h];
        }
#pragma unroll
        for (int off = 16; off; off >>= 1) {
            a0 += __shfl_xor_sync(0xffffffffu, a0, off);
            a1 += __shfl_xor_sync(0xffffffffu, a1, off);
            a2 += __shfl_xor_sync(0xffffffffu, a2, off);
            a3 += __shfl_xor_sync(0xffffffffu, a3, off);
        }
        if (lane < 4) {
            float v = (lane == 0) ? a0 : (lane == 1) ? a1 : (lane == 2) ? a2 : a3;
            v = sigf(v + b2[256 + lane]);
            out[((64 * 160 + i) * 160 + j) * 4 + lane] = v;
        }
    }
}

// ---------------------------------------------------------------------------
extern "C" void kernel_launch(void* const* d_in, const int* in_sizes, int n_in,
                              void* d_out, int out_size) {
    const float* y  = (const float*)d_in[0];
    // d_in[1] = event_idx (unused by reference)
    const float* W1 = (const float*)d_in[2];
    const float* b1 = (const float*)d_in[3];
    const float* W2 = (const float*)d_in[4];
    const float* b2 = (const float*)d_in[5];
    float* out = (float*)d_out;

    rope_kernel<<<160, 384>>>(y);
    lr_kernel<<<dim3(5, 12), 256>>>(W1, b1);
    tail_kernel<<<160, 256>>>(W2, b2, out);
    main_kernel<<<dim3(200, 2), 256>>>(W2, b2, out);
}